// round 1
// baseline (speedup 1.0000x reference)
#include <cuda_runtime.h>
#include <math.h>

// ---------------- problem constants ----------------
#define Bb   4
#define Ss   2048
#define Dd   1024
#define Cc   32
#define Nn   2
#define Ll   128
#define Hh   16
#define DKk  64
#define CHK  64
#define VALID_ROWS 1985            // S - CHUNK + 1
#define MQ  (Bb*Cc*CHK)            // 8192  query rows
#define MKV (Bb*Cc*Nn*Ll)          // 32768 key/value rows
#define NKEY (Nn*Ll)               // 256 keys per chunk

__device__ float g_hs[(size_t)MQ * Dd];   // layernormed+padded chunk stream
__device__ float g_q [(size_t)MQ * Dd];
__device__ float g_k [(size_t)MKV * Dd];
__device__ float g_v [(size_t)MKV * Dd];
__device__ float g_ao[(size_t)MQ * Dd];   // attention output
__device__ float g_po[(size_t)MQ * Dd];   // output projection

// ---------------- LayerNorm + pad ----------------
__global__ __launch_bounds__(256) void ln_kernel(const float* __restrict__ h,
                                                 const float* __restrict__ gamma,
                                                 const float* __restrict__ beta)
{
    int row = blockIdx.x;            // 0..8191  == b*2048 + t
    int b = row >> 11;
    int t = row & 2047;
    float* dst = g_hs + (size_t)row * Dd;
    if (t >= VALID_ROWS) {           // zero padding rows
        ((float4*)dst)[threadIdx.x] = make_float4(0.f, 0.f, 0.f, 0.f);
        return;
    }
    const float* src = h + ((size_t)b * Ss + t + CHK - 1) * Dd;
    float4 x = ((const float4*)src)[threadIdx.x];
    float s  = x.x + x.y + x.z + x.w;
    float ss = x.x*x.x + x.y*x.y + x.z*x.z + x.w*x.w;

    __shared__ float bs[8], bss[8];
    int lane = threadIdx.x & 31, w = threadIdx.x >> 5;
    #pragma unroll
    for (int o = 16; o; o >>= 1) {
        s  += __shfl_down_sync(0xffffffffu, s,  o);
        ss += __shfl_down_sync(0xffffffffu, ss, o);
    }
    if (lane == 0) { bs[w] = s; bss[w] = ss; }
    __syncthreads();
    if (w == 0) {
        s  = (lane < 8) ? bs[lane]  : 0.f;
        ss = (lane < 8) ? bss[lane] : 0.f;
        #pragma unroll
        for (int o = 4; o; o >>= 1) {
            s  += __shfl_down_sync(0xffffffffu, s,  o);
            ss += __shfl_down_sync(0xffffffffu, ss, o);
        }
        if (lane == 0) { bs[0] = s; bss[0] = ss; }
    }
    __syncthreads();
    float mu  = bs[0] * (1.0f / Dd);
    float var = bss[0] * (1.0f / Dd) - mu * mu;
    float inv = rsqrtf(var + 1e-5f);

    float4 g4 = ((const float4*)gamma)[threadIdx.x];
    float4 b4 = ((const float4*)beta)[threadIdx.x];
    float4 o;
    o.x = (x.x - mu) * inv * g4.x + b4.x;
    o.y = (x.y - mu) * inv * g4.y + b4.y;
    o.z = (x.z - mu) * inv * g4.z + b4.z;
    o.w = (x.w - mu) * inv * g4.w + b4.w;
    ((float4*)dst)[threadIdx.x] = o;
}

// ---------------- fp32 SGEMM: C = A(MxK) * W(KxN) + bias ----------------
// 128x128 block tile, BK=16, 256 threads, 8x8 microtile (split 4+4).
__global__ __launch_bounds__(256) void sgemm_bias(const float* __restrict__ A,
                                                  const float* __restrict__ W,
                                                  const float* __restrict__ bias,
                                                  float* __restrict__ Cmat,
                                                  int M, int N, int K)
{
    __shared__ float As[16][128];   // transposed: As[k][m]
    __shared__ float Bs[16][128];

    int tid = threadIdx.x;
    int tx = tid & 15, ty = tid >> 4;
    int m0 = blockIdx.y * 128, n0 = blockIdx.x * 128;

    float acc[8][8];
    #pragma unroll
    for (int i = 0; i < 8; i++)
        #pragma unroll
        for (int j = 0; j < 8; j++) acc[i][j] = 0.f;

    int a_m = tid >> 2;            // 0..63
    int a_k = (tid & 3) << 2;      // 0,4,8,12
    int b_k = tid >> 5;            // 0..7
    int b_n = (tid & 31) << 2;     // 0..124

    const float* Ab = A + (size_t)m0 * K;

    for (int k0 = 0; k0 < K; k0 += 16) {
        float4 a0 = *(const float4*)(Ab + (size_t)a_m        * K + k0 + a_k);
        float4 a1 = *(const float4*)(Ab + (size_t)(a_m + 64) * K + k0 + a_k);
        float4 w0 = *(const float4*)(W + (size_t)(k0 + b_k)     * N + n0 + b_n);
        float4 w1 = *(const float4*)(W + (size_t)(k0 + b_k + 8) * N + n0 + b_n);

        __syncthreads();
        As[a_k + 0][a_m]      = a0.x;  As[a_k + 1][a_m]      = a0.y;
        As[a_k + 2][a_m]      = a0.z;  As[a_k + 3][a_m]      = a0.w;
        As[a_k + 0][a_m + 64] = a1.x;  As[a_k + 1][a_m + 64] = a1.y;
        As[a_k + 2][a_m + 64] = a1.z;  As[a_k + 3][a_m + 64] = a1.w;
        *(float4*)&Bs[b_k][b_n]     = w0;
        *(float4*)&Bs[b_k + 8][b_n] = w1;
        __syncthreads();

        #pragma unroll
        for (int kk = 0; kk < 16; kk++) {
            float4 t0 = *(const float4*)&As[kk][ty * 4];
            float4 t1 = *(const float4*)&As[kk][64 + ty * 4];
            float4 u0 = *(const float4*)&Bs[kk][tx * 4];
            float4 u1 = *(const float4*)&Bs[kk][64 + tx * 4];
            float ra[8] = {t0.x, t0.y, t0.z, t0.w, t1.x, t1.y, t1.z, t1.w};
            float rb[8] = {u0.x, u0.y, u0.z, u0.w, u1.x, u1.y, u1.z, u1.w};
            #pragma unroll
            for (int i = 0; i < 8; i++)
                #pragma unroll
                for (int j = 0; j < 8; j++)
                    acc[i][j] += ra[i] * rb[j];
        }
    }

    float4 bb0 = *(const float4*)(bias + n0 + tx * 4);
    float4 bb1 = *(const float4*)(bias + n0 + 64 + tx * 4);
    #pragma unroll
    for (int i = 0; i < 8; i++) {
        int m = m0 + ((i < 4) ? (ty * 4 + i) : (60 + ty * 4 + i));
        float* crow = Cmat + (size_t)m * N + n0;
        float4 o0 = make_float4(acc[i][0] + bb0.x, acc[i][1] + bb0.y,
                                acc[i][2] + bb0.z, acc[i][3] + bb0.w);
        float4 o1 = make_float4(acc[i][4] + bb1.x, acc[i][5] + bb1.y,
                                acc[i][6] + bb1.z, acc[i][7] + bb1.w);
        *(float4*)(crow + tx * 4)      = o0;
        *(float4*)(crow + 64 + tx * 4) = o1;
    }
}

// ---------------- attention: per (b,c,h), 64 q x 256 kv, softmax, @v --------
// dyn smem: sq 64x65, sc 64x257, kv 64x64  => 98816 bytes
#define ATTN_SMEM ((64*65 + 64*257 + 64*64) * 4)

__global__ __launch_bounds__(256) void attn_kernel()
{
    int blk = blockIdx.x;                 // b*C*H + c*H + h
    int h = blk % Hh;
    int c = (blk / Hh) % Cc;
    int b = blk / (Hh * Cc);

    extern __shared__ float sm[];
    float* sq = sm;                       // stride 65
    float* sc = sm + 64 * 65;             // stride 257
    float* kv = sc + 64 * 257;            // stride 64

    int tid = threadIdx.x;
    const float* qbase = g_q + ((size_t)(b * 2048 + c * 64)) * 1024 + h * 64;
    const float* kbase = g_k + ((size_t)(b * 8192 + c * 256)) * 1024 + h * 64;
    const float* vbase = g_v + ((size_t)(b * 8192 + c * 256)) * 1024 + h * 64;

    // load q tile (64x64) into sq
    for (int idx = tid; idx < 64 * 16; idx += 256) {
        int i = idx >> 4; int d4 = (idx & 15) << 2;
        float4 v4 = *(const float4*)(qbase + (size_t)i * 1024 + d4);
        sq[i * 65 + d4 + 0] = v4.x; sq[i * 65 + d4 + 1] = v4.y;
        sq[i * 65 + d4 + 2] = v4.z; sq[i * 65 + d4 + 3] = v4.w;
    }

    int i_s = tid & 63;                   // score row
    int g   = tid >> 6;                   // 0..3
    float qreg[64];

    // ---- scores ----
    for (int jt = 0; jt < 4; jt++) {
        __syncthreads();                  // q visible / kv free
        for (int idx = tid; idx < 64 * 16; idx += 256) {
            int j = idx >> 4; int d4 = (idx & 15) << 2;
            *(float4*)&kv[j * 64 + d4] =
                *(const float4*)(kbase + (size_t)(jt * 64 + j) * 1024 + d4);
        }
        __syncthreads();
        if (jt == 0) {
            #pragma unroll
            for (int d = 0; d < 64; d++) qreg[d] = sq[i_s * 65 + d];
        }
        #pragma unroll 4
        for (int jj = 0; jj < 16; jj++) {
            int j = g * 16 + jj;
            float a = 0.f;
            #pragma unroll
            for (int d = 0; d < 64; d++) a += qreg[d] * kv[j * 64 + d];
            sc[i_s * 257 + jt * 64 + j] = a * 0.125f;   // 1/sqrt(64)
        }
    }
    __syncthreads();

    // ---- softmax over 256, 4 lanes per row ----
    {
        int i = tid >> 2, q4 = tid & 3;
        float* row = sc + i * 257 + q4 * 64;
        float m = -1e30f;
        #pragma unroll 8
        for (int j = 0; j < 64; j++) m = fmaxf(m, row[j]);
        m = fmaxf(m, __shfl_xor_sync(0xffffffffu, m, 1));
        m = fmaxf(m, __shfl_xor_sync(0xffffffffu, m, 2));
        float s = 0.f;
        #pragma unroll 8
        for (int j = 0; j < 64; j++) { float e = __expf(row[j] - m); row[j] = e; s += e; }
        s += __shfl_xor_sync(0xffffffffu, s, 1);
        s += __shfl_xor_sync(0xffffffffu, s, 2);
        float inv = 1.f / s;
        #pragma unroll 8
        for (int j = 0; j < 64; j++) row[j] *= inv;
    }

    // ---- out = attn @ v ----
    float acc[16];
    #pragma unroll
    for (int t = 0; t < 16; t++) acc[t] = 0.f;
    int io = tid & 63, d0 = (tid >> 6) << 4;

    for (int jt = 0; jt < 4; jt++) {
        __syncthreads();                  // kv free (prev readers done)
        for (int idx = tid; idx < 64 * 16; idx += 256) {
            int j = idx >> 4; int d4 = (idx & 15) << 2;
            *(float4*)&kv[j * 64 + d4] =
                *(const float4*)(vbase + (size_t)(jt * 64 + j) * 1024 + d4);
        }
        __syncthreads();
        #pragma unroll 4
        for (int j = 0; j < 64; j++) {
            float sv = sc[io * 257 + jt * 64 + j];
            #pragma unroll
            for (int dd = 0; dd < 16; dd++)
                acc[dd] += sv * kv[j * 64 + d0 + dd];
        }
    }

    float* obase = g_ao + ((size_t)(b * 2048 + c * 64 + io)) * 1024 + h * 64 + d0;
    #pragma unroll
    for (int dd = 0; dd < 16; dd += 4)
        *(float4*)(obase + dd) = make_float4(acc[dd], acc[dd+1], acc[dd+2], acc[dd+3]);
}

// ---------------- final: shift + residual ----------------
__global__ __launch_bounds__(256) void finalize_kernel(const float* __restrict__ h,
                                                       float* __restrict__ out)
{
    size_t idx = (size_t)blockIdx.x * blockDim.x + threadIdx.x;   // float4 index
    float4 r = ((const float4*)h)[idx];
    size_t fl = idx << 2;
    size_t row = fl >> 10;          // b*2048 + s
    int s = (int)(row & 2047);
    if (s >= 63) {
        size_t srow = row - 63;     // same batch since s-63 >= 0
        const float4 p = *(const float4*)(g_po + srow * 1024 + (fl & 1023));
        r.x += p.x; r.y += p.y; r.z += p.z; r.w += p.w;
    }
    ((float4*)out)[idx] = r;
}

// ---------------- launch ----------------
extern "C" void kernel_launch(void* const* d_in, const int* in_sizes, int n_in,
                              void* d_out, int out_size)
{
    const float* h     = (const float*)d_in[0];
    const float* e     = (const float*)d_in[1];
    const float* Wq    = (const float*)d_in[2];
    const float* bq    = (const float*)d_in[3];
    const float* Wk    = (const float*)d_in[4];
    const float* bk    = (const float*)d_in[5];
    const float* Wv    = (const float*)d_in[6];
    const float* bv    = (const float*)d_in[7];
    const float* Wo    = (const float*)d_in[8];
    const float* bo    = (const float*)d_in[9];
    const float* gamma = (const float*)d_in[10];
    const float* beta  = (const float*)d_in[11];
    float* out = (float*)d_out;

    cudaFuncSetAttribute(attn_kernel,
                         cudaFuncAttributeMaxDynamicSharedMemorySize, ATTN_SMEM);

    float *hs_p, *q_p, *k_p, *v_p, *ao_p, *po_p;
    cudaGetSymbolAddress((void**)&hs_p, g_hs);
    cudaGetSymbolAddress((void**)&q_p,  g_q);
    cudaGetSymbolAddress((void**)&k_p,  g_k);
    cudaGetSymbolAddress((void**)&v_p,  g_v);
    cudaGetSymbolAddress((void**)&ao_p, g_ao);
    cudaGetSymbolAddress((void**)&po_p, g_po);

    ln_kernel<<<MQ, 256>>>(h, gamma, beta);

    dim3 gq(Dd / 128, MQ / 128);            // (8, 64)
    sgemm_bias<<<gq, 256>>>(hs_p, Wq, bq, q_p, MQ, Dd, Dd);

    dim3 gkv(Dd / 128, MKV / 128);          // (8, 256)
    sgemm_bias<<<gkv, 256>>>(e, Wk, bk, k_p, MKV, Dd, Dd);
    sgemm_bias<<<gkv, 256>>>(e, Wv, bv, v_p, MKV, Dd, Dd);

    attn_kernel<<<Bb * Cc * Hh, 256, ATTN_SMEM>>>();

    sgemm_bias<<<gq, 256>>>(ao_p, Wo, bo, po_p, MQ, Dd, Dd);

    finalize_kernel<<<(Bb * Ss * Dd / 4) / 256, 256>>>(h, out);
}

// round 6
// speedup vs baseline: 3.2512x; 3.2512x over previous
#include <cuda_runtime.h>
#include <cuda_bf16.h>
#include <math.h>
#include <stdint.h>

// ---------------- problem constants ----------------
#define Bb   4
#define Ss   2048
#define Dd   1024
#define Cc   32
#define Hh   16
#define CHK  64
#define VALID_ROWS 1985            // S - CHUNK + 1
#define MQ  (Bb*Cc*CHK)            // 8192  query rows
#define MKV (Bb*Cc*2*128)          // 32768 key/value rows

// ---------------- global scratch ----------------
__device__ __nv_bfloat16 g_hs [(size_t)MQ  * Dd];
__device__ __nv_bfloat16 g_e16[(size_t)MKV * Dd];
__device__ __nv_bfloat16 g_wt [4][(size_t)Dd * Dd];   // transposed bf16 weights [N,K]
__device__ float g_q [(size_t)MQ  * Dd];
__device__ float g_k [(size_t)MKV * Dd];
__device__ float g_v [(size_t)MKV * Dd];
__device__ __nv_bfloat16 g_ao[(size_t)MQ * Dd];
__device__ float g_po[(size_t)MQ * Dd];

// ---------------- PTX helpers (baseline sm_100 ISA only) ----------------
__device__ __forceinline__ void cp16(uint32_t dst, const void* src) {
    asm volatile("cp.async.cg.shared.global [%0], [%1], 16;" :: "r"(dst), "l"(src));
}

__device__ __forceinline__ void ldm4(uint32_t* r, uint32_t addr) {
    asm volatile("ldmatrix.sync.aligned.m8n8.x4.shared.b16 {%0,%1,%2,%3}, [%4];"
                 : "=r"(r[0]), "=r"(r[1]), "=r"(r[2]), "=r"(r[3]) : "r"(addr));
}

__device__ __forceinline__ void mma16816(float* c, const uint32_t* a, const uint32_t* b) {
    asm volatile("mma.sync.aligned.m16n8k16.row.col.f32.bf16.bf16.f32 "
                 "{%0,%1,%2,%3}, {%4,%5,%6,%7}, {%8,%9}, {%0,%1,%2,%3};"
                 : "+f"(c[0]), "+f"(c[1]), "+f"(c[2]), "+f"(c[3])
                 : "r"(a[0]), "r"(a[1]), "r"(a[2]), "r"(a[3]), "r"(b[0]), "r"(b[1]));
}

// ---------------- weight transpose + bf16 convert: Wt[n][k] = W[k][n] ------
__global__ __launch_bounds__(256) void wtrans_kernel(const float* __restrict__ W,
                                                     __nv_bfloat16* __restrict__ Wt)
{
    __shared__ float t[32][33];
    int bx = blockIdx.x, by = blockIdx.y;
    int tx = threadIdx.x & 31, ty = threadIdx.x >> 5;   // ty 0..7
    #pragma unroll
    for (int r = 0; r < 4; r++)
        t[ty * 4 + r][tx] = W[(size_t)(by * 32 + ty * 4 + r) * 1024 + bx * 32 + tx];
    __syncthreads();
    #pragma unroll
    for (int r = 0; r < 4; r++)
        Wt[(size_t)(bx * 32 + ty * 4 + r) * 1024 + by * 32 + tx] =
            __float2bfloat16(t[tx][ty * 4 + r]);
}

// ---------------- fp32 -> bf16 convert (for e) ----------------
__global__ __launch_bounds__(256) void f2b_kernel(const float* __restrict__ s,
                                                  __nv_bfloat16* __restrict__ d)
{
    size_t i = (size_t)blockIdx.x * 256 + threadIdx.x;
    float4 v = ((const float4*)s)[i];
    __nv_bfloat162* dp = (__nv_bfloat162*)d + i * 2;
    dp[0] = __floats2bfloat162_rn(v.x, v.y);
    dp[1] = __floats2bfloat162_rn(v.z, v.w);
}

// ---------------- LayerNorm + pad (bf16 out) ----------------
__global__ __launch_bounds__(256) void ln_kernel(const float* __restrict__ h,
                                                 const float* __restrict__ gamma,
                                                 const float* __restrict__ beta)
{
    int row = blockIdx.x;            // b*2048 + t
    int b = row >> 11;
    int t = row & 2047;
    __nv_bfloat162* dst = (__nv_bfloat162*)(g_hs + (size_t)row * Dd) + threadIdx.x * 2;
    if (t >= VALID_ROWS) {
        __nv_bfloat162 z = __floats2bfloat162_rn(0.f, 0.f);
        dst[0] = z; dst[1] = z;
        return;
    }
    const float* src = h + ((size_t)b * Ss + t + CHK - 1) * Dd;
    float4 x = ((const float4*)src)[threadIdx.x];
    float s  = x.x + x.y + x.z + x.w;
    float ss = x.x*x.x + x.y*x.y + x.z*x.z + x.w*x.w;

    __shared__ float bs[8], bss[8];
    int lane = threadIdx.x & 31, w = threadIdx.x >> 5;
    #pragma unroll
    for (int o = 16; o; o >>= 1) {
        s  += __shfl_down_sync(0xffffffffu, s,  o);
        ss += __shfl_down_sync(0xffffffffu, ss, o);
    }
    if (lane == 0) { bs[w] = s; bss[w] = ss; }
    __syncthreads();
    if (w == 0) {
        s  = (lane < 8) ? bs[lane]  : 0.f;
        ss = (lane < 8) ? bss[lane] : 0.f;
        #pragma unroll
        for (int o = 4; o; o >>= 1) {
            s  += __shfl_down_sync(0xffffffffu, s,  o);
            ss += __shfl_down_sync(0xffffffffu, ss, o);
        }
        if (lane == 0) { bs[0] = s; bss[0] = ss; }
    }
    __syncthreads();
    float mu  = bs[0] * (1.0f / Dd);
    float var = bss[0] * (1.0f / Dd) - mu * mu;
    float inv = rsqrtf(var + 1e-5f);

    float4 g4 = ((const float4*)gamma)[threadIdx.x];
    float4 b4 = ((const float4*)beta)[threadIdx.x];
    dst[0] = __floats2bfloat162_rn((x.x - mu) * inv * g4.x + b4.x,
                                   (x.y - mu) * inv * g4.y + b4.y);
    dst[1] = __floats2bfloat162_rn((x.z - mu) * inv * g4.z + b4.z,
                                   (x.w - mu) * inv * g4.w + b4.w);
}

// ---------------- bf16 tensor-core GEMM via mma.sync ----------------------
// C[M,1024] = A[M,1024] (row-major bf16) @ Wt[1024,1024]^T (K-major bf16) + bias
// BM=128 BN=128 BK=32, 256 threads (4x2 warps, 32x64 per warp), 3-stage cp.async.
#define STAGES   3
#define ASTRIDE  40                       // bf16 elems per smem row (80 B)
#define TILE_B   (128 * ASTRIDE * 2)      // 10240 B per matrix per stage
#define GEMM_SMEM (STAGES * TILE_B * 2)   // 61440 B

__device__ __forceinline__ void gemm_load_stage(int kb, uint32_t sAu, uint32_t sBu,
                                                const char* Ag, const char* Bg, uint32_t sw)
{
    int st = kb % STAGES;
    const char* ag = Ag + kb * 64;
    const char* bg = Bg + kb * 64;
    uint32_t ao = sAu + st * TILE_B + sw;
    uint32_t bo = sBu + st * TILE_B + sw;
    cp16(ao, ag);       cp16(ao + 16, ag + 16);
    cp16(bo, bg);       cp16(bo + 16, bg + 16);
}

__global__ __launch_bounds__(256, 1) void gemm_mma(const __nv_bfloat16* __restrict__ A,
                                                   const __nv_bfloat16* __restrict__ Bt,
                                                   const float* __restrict__ bias,
                                                   float* __restrict__ C)
{
    extern __shared__ char smraw[];
    uint32_t sAu = (uint32_t)__cvta_generic_to_shared(smraw);
    uint32_t sBu = sAu + STAGES * TILE_B;

    int tid = threadIdx.x;
    int wid = tid >> 5, lane = tid & 31;
    int wm = wid & 3, wn = wid >> 2;          // warp tile (wm*32, wn*64)
    int m0 = blockIdx.y << 7, n0 = blockIdx.x << 7;

    // cp.async geometry: thread -> row tid/2, two 16B chunks
    int lr = tid >> 1;
    int lc = (tid & 1) * 2;
    const char* Ag = (const char*)(A  + (size_t)(m0 + lr) * 1024) + lc * 16;
    const char* Bg = (const char*)(Bt + (size_t)(n0 + lr) * 1024) + lc * 16;
    uint32_t sw = (uint32_t)lr * 80 + lc * 16;

    gemm_load_stage(0, sAu, sBu, Ag, Bg, sw);
    asm volatile("cp.async.commit_group;" ::: "memory");
    gemm_load_stage(1, sAu, sBu, Ag, Bg, sw);
    asm volatile("cp.async.commit_group;" ::: "memory");

    // ldmatrix lane offsets (bytes)
    uint32_t off_a = (uint32_t)(wm * 32 + (lane & 15)) * 80 + (lane >> 4) * 16;
    uint32_t off_b = (uint32_t)(wn * 64 + (lane & 7) + ((lane >> 4) & 1) * 8) * 80
                   + ((lane >> 3) & 1) * 16;

    float acc[2][8][4];
    #pragma unroll
    for (int i = 0; i < 2; i++)
        #pragma unroll
        for (int j = 0; j < 8; j++)
            #pragma unroll
            for (int k = 0; k < 4; k++) acc[i][j][k] = 0.f;

    for (int kb = 0; kb < 32; kb++) {
        asm volatile("cp.async.wait_group %0;" :: "n"(1) : "memory");
        __syncthreads();
        if (kb + 2 < 32)
            gemm_load_stage(kb + 2, sAu, sBu, Ag, Bg, sw);
        asm volatile("cp.async.commit_group;" ::: "memory");

        uint32_t sAst = sAu + (kb % STAGES) * TILE_B;
        uint32_t sBst = sBu + (kb % STAGES) * TILE_B;
        #pragma unroll
        for (int ks = 0; ks < 2; ks++) {
            uint32_t a[2][4], b[4][4];
            ldm4(a[0], sAst + off_a + ks * 32);
            ldm4(a[1], sAst + off_a + 1280 + ks * 32);     // +16 rows * 80B
            #pragma unroll
            for (int nt = 0; nt < 4; nt++)
                ldm4(b[nt], sBst + off_b + nt * 1280 + ks * 32);
            #pragma unroll
            for (int mt = 0; mt < 2; mt++)
                #pragma unroll
                for (int nt = 0; nt < 4; nt++) {
                    mma16816(acc[mt][2 * nt],     a[mt], &b[nt][0]);
                    mma16816(acc[mt][2 * nt + 1], a[mt], &b[nt][2]);
                }
        }
        __syncthreads();
    }

    // epilogue: direct fp32 stores + bias
    int r0 = m0 + wm * 32 + (lane >> 2);
    int c0 = n0 + wn * 64 + (lane & 3) * 2;
    #pragma unroll
    for (int mt = 0; mt < 2; mt++) {
        int r = r0 + mt * 16;
        #pragma unroll
        for (int j = 0; j < 8; j++) {
            int n = c0 + j * 8;
            float b0 = __ldg(bias + n), b1 = __ldg(bias + n + 1);
            float2 lo = make_float2(acc[mt][j][0] + b0, acc[mt][j][1] + b1);
            float2 hi = make_float2(acc[mt][j][2] + b0, acc[mt][j][3] + b1);
            *(float2*)(C + (size_t)r * 1024 + n)       = lo;
            *(float2*)(C + (size_t)(r + 8) * 1024 + n) = hi;
        }
    }
}

// ---------------- attention: per (b,c,h), 64 q x 256 kv, softmax, @v --------
#define ATTN_SMEM ((64*65 + 64*257 + 64*64) * 4)

__global__ __launch_bounds__(256) void attn_kernel()
{
    int blk = blockIdx.x;
    int h = blk % Hh;
    int c = (blk / Hh) % Cc;
    int b = blk / (Hh * Cc);

    extern __shared__ float sm[];
    float* sq = sm;                       // stride 65
    float* sc = sm + 64 * 65;             // stride 257
    float* kv = sc + 64 * 257;            // stride 64

    int tid = threadIdx.x;
    const float* qbase = g_q + ((size_t)(b * 2048 + c * 64)) * 1024 + h * 64;
    const float* kbase = g_k + ((size_t)(b * 8192 + c * 256)) * 1024 + h * 64;
    const float* vbase = g_v + ((size_t)(b * 8192 + c * 256)) * 1024 + h * 64;

    for (int idx = tid; idx < 64 * 16; idx += 256) {
        int i = idx >> 4; int d4 = (idx & 15) << 2;
        float4 v4 = *(const float4*)(qbase + (size_t)i * 1024 + d4);
        sq[i * 65 + d4 + 0] = v4.x; sq[i * 65 + d4 + 1] = v4.y;
        sq[i * 65 + d4 + 2] = v4.z; sq[i * 65 + d4 + 3] = v4.w;
    }

    int i_s = tid & 63;
    int g   = tid >> 6;
    float qreg[64];

    for (int jt = 0; jt < 4; jt++) {
        __syncthreads();
        for (int idx = tid; idx < 64 * 16; idx += 256) {
            int j = idx >> 4; int d4 = (idx & 15) << 2;
            *(float4*)&kv[j * 64 + d4] =
                *(const float4*)(kbase + (size_t)(jt * 64 + j) * 1024 + d4);
        }
        __syncthreads();
        if (jt == 0) {
            #pragma unroll
            for (int d = 0; d < 64; d++) qreg[d] = sq[i_s * 65 + d];
        }
        #pragma unroll 4
        for (int jj = 0; jj < 16; jj++) {
            int j = g * 16 + jj;
            float a = 0.f;
            #pragma unroll
            for (int d = 0; d < 64; d++) a += qreg[d] * kv[j * 64 + d];
            sc[i_s * 257 + jt * 64 + j] = a * 0.125f;
        }
    }
    __syncthreads();

    {
        int i = tid >> 2, q4 = tid & 3;
        float* row = sc + i * 257 + q4 * 64;
        float m = -1e30f;
        #pragma unroll 8
        for (int j = 0; j < 64; j++) m = fmaxf(m, row[j]);
        m = fmaxf(m, __shfl_xor_sync(0xffffffffu, m, 1));
        m = fmaxf(m, __shfl_xor_sync(0xffffffffu, m, 2));
        float s = 0.f;
        #pragma unroll 8
        for (int j = 0; j < 64; j++) { float e = __expf(row[j] - m); row[j] = e; s += e; }
        s += __shfl_xor_sync(0xffffffffu, s, 1);
        s += __shfl_xor_sync(0xffffffffu, s, 2);
        float inv = 1.f / s;
        #pragma unroll 8
        for (int j = 0; j < 64; j++) row[j] *= inv;
    }

    float acc[16];
    #pragma unroll
    for (int t = 0; t < 16; t++) acc[t] = 0.f;
    int io = tid & 63, d0 = (tid >> 6) << 4;

    for (int jt = 0; jt < 4; jt++) {
        __syncthreads();
        for (int idx = tid; idx < 64 * 16; idx += 256) {
            int j = idx >> 4; int d4 = (idx & 15) << 2;
            *(float4*)&kv[j * 64 + d4] =
                *(const float4*)(vbase + (size_t)(jt * 64 + j) * 1024 + d4);
        }
        __syncthreads();
        #pragma unroll 4
        for (int j = 0; j < 64; j++) {
            float sv = sc[io * 257 + jt * 64 + j];
            #pragma unroll
            for (int dd = 0; dd < 16; dd++)
                acc[dd] += sv * kv[j * 64 + d0 + dd];
        }
    }

    __nv_bfloat16* ob = g_ao + ((size_t)(b * 2048 + c * 64 + io)) * 1024 + h * 64 + d0;
    #pragma unroll
    for (int dd = 0; dd < 16; dd += 2)
        *(__nv_bfloat162*)(ob + dd) = __floats2bfloat162_rn(acc[dd], acc[dd + 1]);
}

// ---------------- final: shift + residual ----------------
__global__ __launch_bounds__(256) void finalize_kernel(const float* __restrict__ h,
                                                       float* __restrict__ out)
{
    size_t idx = (size_t)blockIdx.x * blockDim.x + threadIdx.x;   // float4 index
    float4 r = ((const float4*)h)[idx];
    size_t fl = idx << 2;
    size_t row = fl >> 10;
    int s = (int)(row & 2047);
    if (s >= 63) {
        size_t srow = row - 63;
        const float4 p = *(const float4*)(g_po + srow * 1024 + (fl & 1023));
        r.x += p.x; r.y += p.y; r.z += p.z; r.w += p.w;
    }
    ((float4*)out)[idx] = r;
}

// ---------------- launch ----------------
extern "C" void kernel_launch(void* const* d_in, const int* in_sizes, int n_in,
                              void* d_out, int out_size)
{
    const float* h     = (const float*)d_in[0];
    const float* e     = (const float*)d_in[1];
    const float* Wq    = (const float*)d_in[2];
    const float* bq    = (const float*)d_in[3];
    const float* Wk    = (const float*)d_in[4];
    const float* bk    = (const float*)d_in[5];
    const float* Wv    = (const float*)d_in[6];
    const float* bv    = (const float*)d_in[7];
    const float* Wo    = (const float*)d_in[8];
    const float* bo    = (const float*)d_in[9];
    const float* gamma = (const float*)d_in[10];
    const float* beta  = (const float*)d_in[11];
    float* out = (float*)d_out;

    cudaFuncSetAttribute(attn_kernel, cudaFuncAttributeMaxDynamicSharedMemorySize, ATTN_SMEM);
    cudaFuncSetAttribute(gemm_mma,    cudaFuncAttributeMaxDynamicSharedMemorySize, GEMM_SMEM);

    __nv_bfloat16 *hs_p, *e16_p, *wt_p, *ao_p;
    float *q_p, *k_p, *v_p, *po_p;
    cudaGetSymbolAddress((void**)&hs_p,  g_hs);
    cudaGetSymbolAddress((void**)&e16_p, g_e16);
    cudaGetSymbolAddress((void**)&wt_p,  g_wt);
    cudaGetSymbolAddress((void**)&q_p,   g_q);
    cudaGetSymbolAddress((void**)&k_p,   g_k);
    cudaGetSymbolAddress((void**)&v_p,   g_v);
    cudaGetSymbolAddress((void**)&ao_p,  g_ao);
    cudaGetSymbolAddress((void**)&po_p,  g_po);

    __nv_bfloat16* wqt = wt_p;
    __nv_bfloat16* wkt = wt_p + (size_t)Dd * Dd;
    __nv_bfloat16* wvt = wt_p + 2 * (size_t)Dd * Dd;
    __nv_bfloat16* wot = wt_p + 3 * (size_t)Dd * Dd;

    dim3 gt(32, 32);
    wtrans_kernel<<<gt, 256>>>(Wq, wqt);
    wtrans_kernel<<<gt, 256>>>(Wk, wkt);
    wtrans_kernel<<<gt, 256>>>(Wv, wvt);
    wtrans_kernel<<<gt, 256>>>(Wo, wot);

    f2b_kernel<<<(size_t)MKV * Dd / 4 / 256, 256>>>(e, e16_p);
    ln_kernel<<<MQ, 256>>>(h, gamma, beta);

    dim3 gq(8, MQ / 128);           // (8, 64)
    dim3 gkv(8, MKV / 128);         // (8, 256)
    gemm_mma<<<gq,  256, GEMM_SMEM>>>(hs_p,  wqt, bq, q_p);
    gemm_mma<<<gkv, 256, GEMM_SMEM>>>(e16_p, wkt, bk, k_p);
    gemm_mma<<<gkv, 256, GEMM_SMEM>>>(e16_p, wvt, bv, v_p);

    attn_kernel<<<Bb * Cc * Hh, 256, ATTN_SMEM>>>();

    gemm_mma<<<gq, 256, GEMM_SMEM>>>(ao_p, wot, bo, po_p);

    finalize_kernel<<<(Bb * Ss * Dd / 4) / 256, 256>>>(h, out);
}